// round 16
// baseline (speedup 1.0000x reference)
#include <cuda_runtime.h>
#include <cuda_bf16.h>
#include <cstdint>

#define B_ROWS 65536
#define D_IN   256
#define D_G    512
#define EPS_BN 1e-5f

// scratch: z = GBN(feat@W^T) * priors
__device__ float g_z[(size_t)B_ROWS * D_G];
// pre-split bf16 hi/lo planes
__device__ __nv_bfloat16 g_ah[(size_t)B_ROWS * D_IN];
__device__ __nv_bfloat16 g_al[(size_t)B_ROWS * D_IN];
__device__ __nv_bfloat16 g_bh[(size_t)D_G   * D_IN];
__device__ __nv_bfloat16 g_bl[(size_t)D_G   * D_IN];

// ---------------------------------------------------------------------------
// helpers (plain compute_103-legal PTX)
// ---------------------------------------------------------------------------
__device__ __forceinline__ uint32_t smem_u32_of(const void* p) {
    uint32_t a;
    asm("{ .reg .u64 t; cvta.to.shared.u64 t, %1; cvt.u32.u64 %0, t; }" : "=r"(a) : "l"(p));
    return a;
}
__device__ __forceinline__ void ldsm_x4(uint32_t* r, uint32_t addr) {
    asm volatile("ldmatrix.sync.aligned.m8n8.x4.shared.b16 {%0,%1,%2,%3}, [%4];"
                 : "=r"(r[0]), "=r"(r[1]), "=r"(r[2]), "=r"(r[3]) : "r"(addr));
}
__device__ __forceinline__ void mma16816(float* d, const uint32_t* a, const uint32_t* b) {
    asm volatile("mma.sync.aligned.m16n8k16.row.col.f32.bf16.bf16.f32 "
                 "{%0,%1,%2,%3}, {%4,%5,%6,%7}, {%8,%9}, {%0,%1,%2,%3};"
                 : "+f"(d[0]), "+f"(d[1]), "+f"(d[2]), "+f"(d[3])
                 : "r"(a[0]), "r"(a[1]), "r"(a[2]), "r"(a[3]), "r"(b[0]), "r"(b[1]));
}
__device__ __forceinline__ void cp_async16(uint32_t dst, const void* src) {
    asm volatile("cp.async.cg.shared.global [%0], [%1], 16;" :: "r"(dst), "l"(src));
}
__device__ __forceinline__ void cp_commit() {
    asm volatile("cp.async.commit_group;" ::: "memory");
}
template <int N>
__device__ __forceinline__ void cp_wait() {
    asm volatile("cp.async.wait_group %0;" :: "n"(N) : "memory");
}

// smem tile: 128 rows x 64 bf16 cols, row stride 144 B (128B data + 16 pad)
// r*144 mod 128 = r*16 mod 128 -> 8 consecutive rows hit 8 distinct 16B
// groups -> LDSM conflict-free.
#define ROWB    144
#define TILE_B  (128 * ROWB)        // 18432
#define STAGE_B (4 * TILE_B)        // 73728 (Ahi, Alo, Bhi, Blo)
#define NSTAGE  3
#define SMEM_TOTAL (NSTAGE * STAGE_B)   // 221184 <= 227KB opt-in

// ---------------------------------------------------------------------------
// Kernel 0: fp32 -> bf16 hi/lo split (element order preserved, float4-wide)
// ---------------------------------------------------------------------------
__global__ __launch_bounds__(256)
void split_kernel(const float* __restrict__ x,
                  __nv_bfloat16* __restrict__ hi,
                  __nv_bfloat16* __restrict__ lo)
{
    const int i = blockIdx.x * blockDim.x + threadIdx.x;
    const float4 v = ((const float4*)x)[i];
    __nv_bfloat162 h0 = __float22bfloat162_rn(make_float2(v.x, v.y));
    __nv_bfloat162 h1 = __float22bfloat162_rn(make_float2(v.z, v.w));
    __nv_bfloat162 l0 = __float22bfloat162_rn(make_float2(
        v.x - __bfloat162float(h0.x), v.y - __bfloat162float(h0.y)));
    __nv_bfloat162 l1 = __float22bfloat162_rn(make_float2(
        v.z - __bfloat162float(h1.x), v.w - __bfloat162float(h1.y)));
    uint2 uh, ul;
    uh.x = *(uint32_t*)&h0; uh.y = *(uint32_t*)&h1;
    ul.x = *(uint32_t*)&l0; ul.y = *(uint32_t*)&l1;
    ((uint2*)hi)[i] = uh;
    ((uint2*)lo)[i] = ul;
}

// ---------------------------------------------------------------------------
// Kernel 1: pure-bf16 3-term MMA GEMM + GhostBN + priors -> g_z
// Grid (D_G/128, B/128) = (4, 512); 512 threads = 16 warps (4m x 4n),
// warp tile 32x32; K chunks of 64, 3-stage cp.async pipeline.
// ---------------------------------------------------------------------------
__global__ __launch_bounds__(512, 1)
void gemm_gbn_mma(const float* __restrict__ priors,
                  const float* __restrict__ gamma,
                  const float* __restrict__ beta)
{
    extern __shared__ char smem[];
    const uint32_t sbase = smem_u32_of(smem);

    const int tid  = threadIdx.x;
    const int wid  = tid >> 5;      // 0..15
    const int lane = tid & 31;
    const int warp_m = wid >> 2;    // 0..3 -> 32-row stripe
    const int warp_n = wid & 3;     // 0..3 -> 32-col stripe
    const int m0 = blockIdx.y * 128;
    const int n0 = blockIdx.x * 128;

    const __nv_bfloat16* tbase[4] = {
        g_ah + (size_t)m0 * D_IN,
        g_al + (size_t)m0 * D_IN,
        g_bh + (size_t)n0 * D_IN,
        g_bl + (size_t)n0 * D_IN
    };

    // issue one K-chunk (64 cols) into stage c%3: 4 tiles x 128 rows x 4x16B
    auto issue = [&](int c) {
        const uint32_t stg = sbase + (uint32_t)(c % NSTAGE) * STAGE_B;
        const int kt0 = c * 64;
#pragma unroll
        for (int i = 0; i < 8; i++) {
            const int tile = i >> 1;                    // compile-time per i
            const int sub  = ((i & 1) << 9) | tid;      // 0..1023
            const int row  = sub >> 3;                  // 0..127
            const int kc   = sub & 7;                   // 0..7 (16B chunks)
            const __nv_bfloat16* src = tbase[tile] + (size_t)row * D_IN + kt0 + kc * 8;
            cp_async16(stg + tile * TILE_B + row * ROWB + kc * 16, src);
        }
        cp_commit();
    };

    float acc[2][4][4];
#pragma unroll
    for (int f = 0; f < 2; f++)
#pragma unroll
        for (int g = 0; g < 4; g++)
#pragma unroll
            for (int r = 0; r < 4; r++) acc[f][g][r] = 0.0f;

    // per-thread LDSM coords
    const uint32_t a_r = (uint32_t)(warp_m * 32 + (lane & 15));
    const uint32_t a_c = (uint32_t)((lane >> 4) * 8);
    const uint32_t b_row = (uint32_t)(warp_n * 32 + (lane >> 4) * 8 + (lane & 7));
    const uint32_t b_kc  = (uint32_t)(((lane >> 3) & 1) * 8);

    issue(0);
    issue(1);

#pragma unroll
    for (int t = 0; t < 4; ++t) {                 // 4 chunks of K=64
        if (t + 2 < 4) issue(t + 2);
        if      (t <= 1) cp_wait<2>();
        else if (t == 2) cp_wait<1>();
        else             cp_wait<0>();
        __syncthreads();

        const uint32_t stg = sbase + (uint32_t)(t % NSTAGE) * STAGE_B;
        const uint32_t Ahi = stg, Alo = stg + TILE_B;
        const uint32_t Bhi = stg + 2 * TILE_B, Blo = stg + 3 * TILE_B;

#pragma unroll
        for (int s = 0; s < 4; ++s) {             // four k16 steps per chunk
            const uint32_t k0 = (uint32_t)(s * 16);
            uint32_t bh[2][4], bl[2][4];
#pragma unroll
            for (int gp = 0; gp < 2; ++gp) {
                const uint32_t boff = (b_row + gp * 16) * ROWB + (k0 + b_kc) * 2;
                ldsm_x4(bh[gp], Bhi + boff);
                ldsm_x4(bl[gp], Blo + boff);
            }
#pragma unroll
            for (int f = 0; f < 2; ++f) {
                const uint32_t aoff = (a_r + f * 16) * ROWB + (k0 + a_c) * 2;
                uint32_t ah[4], al[4];
                ldsm_x4(ah, Ahi + aoff);
                ldsm_x4(al, Alo + aoff);
#pragma unroll
                for (int g = 0; g < 4; ++g) {
                    const uint32_t* bhp = &bh[g >> 1][(g & 1) * 2];
                    const uint32_t* blp = &bl[g >> 1][(g & 1) * 2];
                    mma16816(acc[f][g], ah, bhp);   // hi*hi
                    mma16816(acc[f][g], ah, blp);   // hi*lo
                    mma16816(acc[f][g], al, bhp);   // lo*hi
                }
            }
        }
        __syncthreads();    // stage t%3 reused by chunk t+3 (issued next iter)
    }

    // ---------------- GhostBN epilogue ----------------
    float* Psum   = (float*)smem;                 // 32 x 128
    float* Psq    = (float*)(smem + 16384);
    float* cscale = (float*)(smem + 32768);
    float* cshift = (float*)(smem + 33280);

    const int prow  = warp_m * 8 + (lane >> 2);         // 0..31
    const int cbase = warp_n * 32 + (lane & 3) * 2;     // even col of this lane

#pragma unroll
    for (int g = 0; g < 4; ++g) {
        float se = 0.f, so = 0.f, qe = 0.f, qo = 0.f;
#pragma unroll
        for (int f = 0; f < 2; ++f) {
            const float e0 = acc[f][g][0], e1 = acc[f][g][2];
            const float o0 = acc[f][g][1], o1 = acc[f][g][3];
            se += e0 + e1;  qe += e0 * e0 + e1 * e1;
            so += o0 + o1;  qo += o0 * o0 + o1 * o1;
        }
        Psum[prow * 128 + cbase + g * 8]     = se;
        Psum[prow * 128 + cbase + g * 8 + 1] = so;
        Psq [prow * 128 + cbase + g * 8]     = qe;
        Psq [prow * 128 + cbase + g * 8 + 1] = qo;
    }
    __syncthreads();

    if (tid < 128) {
        float s = 0.f, s2 = 0.f;
#pragma unroll
        for (int r = 0; r < 32; r++) {
            s  += Psum[r * 128 + tid];
            s2 += Psq [r * 128 + tid];
        }
        const float mean = s * (1.0f / 128.0f);
        const float var  = s2 * (1.0f / 128.0f) - mean * mean;
        const float sc   = gamma[n0 + tid] * rsqrtf(var + EPS_BN);
        cscale[tid] = sc;
        cshift[tid] = beta[n0 + tid] - mean * sc;
    }
    __syncthreads();

#pragma unroll
    for (int g = 0; g < 4; ++g) {
        const int cl = cbase + g * 8;
        const float2 sc = *(const float2*)&cscale[cl];
        const float2 sh = *(const float2*)&cshift[cl];
        const int col = n0 + cl;
#pragma unroll
        for (int f = 0; f < 2; ++f) {
            const int row0 = m0 + warp_m * 32 + f * 16 + (lane >> 2);
#pragma unroll
            for (int h = 0; h < 2; ++h) {
                const size_t row = (size_t)(row0 + h * 8);
                const float2 p = *(const float2*)&priors[row * D_G + col];
                float2 z;
                z.x = fmaf(acc[f][g][h * 2 + 0], sc.x, sh.x) * p.x;
                z.y = fmaf(acc[f][g][h * 2 + 1], sc.y, sh.y) * p.y;
                *(float2*)&g_z[row * D_G + col] = z;
            }
        }
    }
}

// ---------------------------------------------------------------------------
// Kernel 2: sparsemax per row (D=512), Michelot fixed point. Warp per row.
// ---------------------------------------------------------------------------
__global__ __launch_bounds__(256)
void sparsemax_kernel(float* __restrict__ out)
{
    const int gw   = (blockIdx.x * blockDim.x + threadIdx.x) >> 5;
    const int lane = threadIdx.x & 31;
    const float4* zr = (const float4*)(g_z + (size_t)gw * D_G);

    float4 v[4];
#pragma unroll
    for (int c = 0; c < 4; c++) v[c] = zr[c * 32 + lane];

    float mx = fmaxf(fmaxf(v[0].x, v[0].y), fmaxf(v[0].z, v[0].w));
#pragma unroll
    for (int c = 1; c < 4; c++)
        mx = fmaxf(mx, fmaxf(fmaxf(v[c].x, v[c].y), fmaxf(v[c].z, v[c].w)));
#pragma unroll
    for (int o = 16; o > 0; o >>= 1)
        mx = fmaxf(mx, __shfl_xor_sync(0xffffffffu, mx, o));

    float s = 0.0f;
#pragma unroll
    for (int c = 0; c < 4; c++) {
        v[c].x -= mx; v[c].y -= mx; v[c].z -= mx; v[c].w -= mx;
        s += (v[c].x + v[c].y) + (v[c].z + v[c].w);
    }
#pragma unroll
    for (int o = 16; o > 0; o >>= 1)
        s += __shfl_xor_sync(0xffffffffu, s, o);

    float tau = (s - 1.0f) * (1.0f / 512.0f);

    for (int it = 0; it < 64; ++it) {
        float ns = 0.0f;
        unsigned k = 0;
#pragma unroll
        for (int c = 0; c < 4; c++) {
            if (v[c].x > tau) { ns += v[c].x; k++; }
            if (v[c].y > tau) { ns += v[c].y; k++; }
            if (v[c].z > tau) { ns += v[c].z; k++; }
            if (v[c].w > tau) { ns += v[c].w; k++; }
        }
#pragma unroll
        for (int o = 16; o > 0; o >>= 1)
            ns += __shfl_xor_sync(0xffffffffu, ns, o);
        k = __reduce_add_sync(0xffffffffu, k);

        const float nt = (ns - 1.0f) / (float)k;
        if (nt == tau) break;
        tau = nt;
    }

    float4* orow = (float4*)(out + (size_t)gw * D_G);
#pragma unroll
    for (int c = 0; c < 4; c++) {
        float4 r;
        r.x = fmaxf(v[c].x - tau, 0.0f);
        r.y = fmaxf(v[c].y - tau, 0.0f);
        r.z = fmaxf(v[c].z - tau, 0.0f);
        r.w = fmaxf(v[c].w - tau, 0.0f);
        orow[c * 32 + lane] = r;
    }
}

// ---------------------------------------------------------------------------
extern "C" void kernel_launch(void* const* d_in, const int* in_sizes, int n_in,
                              void* d_out, int out_size)
{
    const float* priors = (const float*)d_in[0];   // [B, 512]
    const float* feat   = (const float*)d_in[1];   // [B, 256]
    const float* W      = (const float*)d_in[2];   // [512, 256]
    const float* gamma  = (const float*)d_in[3];   // [512]
    const float* beta   = (const float*)d_in[4];   // [512]
    float* out = (float*)d_out;                    // [B, 512]

    // resolve device-global symbol addresses (host side, capture-safe)
    __nv_bfloat16 *ah, *al, *bh, *bl;
    cudaGetSymbolAddress((void**)&ah, g_ah);
    cudaGetSymbolAddress((void**)&al, g_al);
    cudaGetSymbolAddress((void**)&bh, g_bh);
    cudaGetSymbolAddress((void**)&bl, g_bl);

    // split feat: 65536*256/4 float4 -> 16384 blocks; W: 512*256/4 -> 128 blocks
    split_kernel<<<(B_ROWS * D_IN / 4) / 256, 256>>>(feat, ah, al);
    split_kernel<<<(D_G * D_IN / 4) / 256, 256>>>(W, bh, bl);

    cudaFuncSetAttribute(gemm_gbn_mma,
                         cudaFuncAttributeMaxDynamicSharedMemorySize, SMEM_TOTAL);

    dim3 grid1(D_G / 128, B_ROWS / 128);           // (4, 512)
    gemm_gbn_mma<<<grid1, 512, SMEM_TOTAL>>>(priors, gamma, beta);

    sparsemax_kernel<<<(B_ROWS * 32) / 256, 256>>>(out);
}

// round 17
// speedup vs baseline: 1.0704x; 1.0704x over previous
#include <cuda_runtime.h>
#include <cuda_bf16.h>
#include <cstdint>

#define B_ROWS 65536
#define D_IN   256
#define D_G    512
#define EPS_BN 1e-5f

// scratch: z = GBN(feat@W^T) * priors
__device__ float g_z[(size_t)B_ROWS * D_G];
// pre-split bf16 hi/lo planes
__device__ __nv_bfloat16 g_ah[(size_t)B_ROWS * D_IN];
__device__ __nv_bfloat16 g_al[(size_t)B_ROWS * D_IN];
__device__ __nv_bfloat16 g_bh[(size_t)D_G   * D_IN];
__device__ __nv_bfloat16 g_bl[(size_t)D_G   * D_IN];

// ---------------------------------------------------------------------------
// helpers (plain compute_103-legal PTX)
// ---------------------------------------------------------------------------
__device__ __forceinline__ uint32_t smem_u32_of(const void* p) {
    uint32_t a;
    asm("{ .reg .u64 t; cvta.to.shared.u64 t, %1; cvt.u32.u64 %0, t; }" : "=r"(a) : "l"(p));
    return a;
}
__device__ __forceinline__ void ldsm_x4(uint32_t* r, uint32_t addr) {
    asm volatile("ldmatrix.sync.aligned.m8n8.x4.shared.b16 {%0,%1,%2,%3}, [%4];"
                 : "=r"(r[0]), "=r"(r[1]), "=r"(r[2]), "=r"(r[3]) : "r"(addr));
}
__device__ __forceinline__ void mma16816(float* d, const uint32_t* a, const uint32_t* b) {
    asm volatile("mma.sync.aligned.m16n8k16.row.col.f32.bf16.bf16.f32 "
                 "{%0,%1,%2,%3}, {%4,%5,%6,%7}, {%8,%9}, {%0,%1,%2,%3};"
                 : "+f"(d[0]), "+f"(d[1]), "+f"(d[2]), "+f"(d[3])
                 : "r"(a[0]), "r"(a[1]), "r"(a[2]), "r"(a[3]), "r"(b[0]), "r"(b[1]));
}
__device__ __forceinline__ void cp_async16(uint32_t dst, const void* src) {
    asm volatile("cp.async.cg.shared.global [%0], [%1], 16;" :: "r"(dst), "l"(src));
}
__device__ __forceinline__ void cp_commit() {
    asm volatile("cp.async.commit_group;" ::: "memory");
}
template <int N>
__device__ __forceinline__ void cp_wait() {
    asm volatile("cp.async.wait_group %0;" :: "n"(N) : "memory");
}

// smem tiles: rows x 32 bf16 cols (64B data), row stride 80B ->
// r*80 mod 128 covers 8 distinct 16B groups over 8 rows -> LDSM conflict-free
#define ROWB     80
#define A_TILE_B (256 * ROWB)                    // 20480
#define B_TILE_B (128 * ROWB)                    // 10240
#define STAGE_B  (2 * A_TILE_B + 2 * B_TILE_B)   // 61440 (Ahi, Alo, Bhi, Blo)
#define NSTAGE   3
#define SMEM_TOTAL (NSTAGE * STAGE_B)            // 184320 <= 227KB opt-in

// ---------------------------------------------------------------------------
// Kernel 0: fp32 -> bf16 hi/lo split (element order preserved, float4-wide)
// ---------------------------------------------------------------------------
__global__ __launch_bounds__(256)
void split_kernel(const float* __restrict__ x,
                  __nv_bfloat16* __restrict__ hi,
                  __nv_bfloat16* __restrict__ lo)
{
    const int i = blockIdx.x * blockDim.x + threadIdx.x;
    const float4 v = ((const float4*)x)[i];
    __nv_bfloat162 h0 = __float22bfloat162_rn(make_float2(v.x, v.y));
    __nv_bfloat162 h1 = __float22bfloat162_rn(make_float2(v.z, v.w));
    __nv_bfloat162 l0 = __float22bfloat162_rn(make_float2(
        v.x - __bfloat162float(h0.x), v.y - __bfloat162float(h0.y)));
    __nv_bfloat162 l1 = __float22bfloat162_rn(make_float2(
        v.z - __bfloat162float(h1.x), v.w - __bfloat162float(h1.y)));
    uint2 uh, ul;
    uh.x = *(uint32_t*)&h0; uh.y = *(uint32_t*)&h1;
    ul.x = *(uint32_t*)&l0; ul.y = *(uint32_t*)&l1;
    ((uint2*)hi)[i] = uh;
    ((uint2*)lo)[i] = ul;
}

// ---------------------------------------------------------------------------
// Kernel 1: pure-bf16 3-term MMA GEMM + GhostBN + priors -> g_z
// CTA tile 256x128 (two ghost batches), 512 threads = 16 warps (4m x 4n),
// warp tile 64x32; K chunks of 32, 3-stage cp.async pipeline.
// Grid (D_G/128, B/256) = (4, 256).
// ---------------------------------------------------------------------------
__global__ __launch_bounds__(512, 1)
void gemm_gbn_mma(const float* __restrict__ priors,
                  const float* __restrict__ gamma,
                  const float* __restrict__ beta)
{
    extern __shared__ char smem[];
    const uint32_t sbase = smem_u32_of(smem);

    const int tid  = threadIdx.x;
    const int wid  = tid >> 5;      // 0..15
    const int lane = tid & 31;
    const int warp_m = wid >> 2;    // 0..3 -> 64-row stripe
    const int warp_n = wid & 3;     // 0..3 -> 32-col stripe
    const int m0 = blockIdx.y * 256;
    const int n0 = blockIdx.x * 128;

    // cp.async source mappings
    const int arow = tid >> 1;                 // 0..255
    const int ac   = (tid & 1) * 2;            // 16B-chunk base (0 or 2)
    const int brow = tid >> 2;                 // 0..127
    const int bc   = tid & 3;                  // 16B chunk

    const __nv_bfloat16* pah = g_ah + (size_t)(m0 + arow) * D_IN;
    const __nv_bfloat16* pal = g_al + (size_t)(m0 + arow) * D_IN;
    const __nv_bfloat16* pbh = g_bh + (size_t)(n0 + brow) * D_IN;
    const __nv_bfloat16* pbl = g_bl + (size_t)(n0 + brow) * D_IN;

    const uint32_t a_dst = (uint32_t)(arow * ROWB + ac * 16);
    const uint32_t b_dst = (uint32_t)(brow * ROWB + bc * 16);

    auto issue = [&](int c) {
        const uint32_t stg = sbase + (uint32_t)(c % NSTAGE) * STAGE_B;
        const int kt0 = c * 32;
        cp_async16(stg + a_dst,                            pah + kt0 + (ac + 0) * 8);
        cp_async16(stg + a_dst + 16,                       pah + kt0 + (ac + 1) * 8);
        cp_async16(stg + A_TILE_B + a_dst,                 pal + kt0 + (ac + 0) * 8);
        cp_async16(stg + A_TILE_B + a_dst + 16,            pal + kt0 + (ac + 1) * 8);
        cp_async16(stg + 2 * A_TILE_B + b_dst,             pbh + kt0 + bc * 8);
        cp_async16(stg + 2 * A_TILE_B + B_TILE_B + b_dst,  pbl + kt0 + bc * 8);
        cp_commit();
    };

    float acc[4][4][4];
#pragma unroll
    for (int f = 0; f < 4; f++)
#pragma unroll
        for (int g = 0; g < 4; g++)
#pragma unroll
            for (int r = 0; r < 4; r++) acc[f][g][r] = 0.0f;

    // per-thread LDSM coords
    const uint32_t a_r = (uint32_t)(warp_m * 64 + (lane & 15));
    const uint32_t a_c = (uint32_t)((lane >> 4) * 8);
    const uint32_t b_row = (uint32_t)(warp_n * 32 + (lane >> 4) * 8 + (lane & 7));
    const uint32_t b_kc  = (uint32_t)(((lane >> 3) & 1) * 8);

    issue(0);
    issue(1);

#pragma unroll
    for (int t = 0; t < 8; ++t) {                 // 8 chunks of K=32
        if (t + 2 < 8) { issue(t + 2); cp_wait<2>(); }
        else if (t == 6) cp_wait<1>();
        else             cp_wait<0>();
        __syncthreads();

        const uint32_t stg = sbase + (uint32_t)(t % NSTAGE) * STAGE_B;
        const uint32_t Ahi = stg, Alo = stg + A_TILE_B;
        const uint32_t Bhi = stg + 2 * A_TILE_B, Blo = Bhi + B_TILE_B;

#pragma unroll
        for (int s = 0; s < 2; ++s) {             // two k16 steps per chunk
            const uint32_t k0 = (uint32_t)(s * 16);
            uint32_t bh[2][4], bl[2][4];
#pragma unroll
            for (int gp = 0; gp < 2; ++gp) {
                const uint32_t boff = (b_row + gp * 16) * ROWB + (k0 + b_kc) * 2;
                ldsm_x4(bh[gp], Bhi + boff);
                ldsm_x4(bl[gp], Blo + boff);
            }
#pragma unroll
            for (int f = 0; f < 4; ++f) {
                const uint32_t aoff = (a_r + f * 16) * ROWB + (k0 + a_c) * 2;
                uint32_t ah[4], al[4];
                ldsm_x4(ah, Ahi + aoff);
                ldsm_x4(al, Alo + aoff);
#pragma unroll
                for (int g = 0; g < 4; ++g) {
                    const uint32_t* bhp = &bh[g >> 1][(g & 1) * 2];
                    const uint32_t* blp = &bl[g >> 1][(g & 1) * 2];
                    mma16816(acc[f][g], ah, bhp);   // hi*hi
                    mma16816(acc[f][g], ah, blp);   // hi*lo
                    mma16816(acc[f][g], al, bhp);   // lo*hi
                }
            }
        }
        __syncthreads();    // stage t%3 refilled by issue(t+3) next iteration
    }

    // ---------------- GhostBN epilogue (two ghost batches) ----------------
    // Psum[2][16][128] @0 (16KB), Psq @16384, cscale[2][128] @32768, cshift @33792
    float* Psum   = (float*)smem;
    float* Psq    = (float*)(smem + 16384);
    float* cscale = (float*)(smem + 32768);
    float* cshift = (float*)(smem + 33792);

    const int gb    = warp_m >> 1;                      // ghost batch within CTA
    const int pr    = (warp_m & 1) * 8 + (lane >> 2);   // 0..15
    const int cbase = warp_n * 32 + (lane & 3) * 2;     // even col of this lane

#pragma unroll
    for (int g = 0; g < 4; ++g) {
        float se = 0.f, so = 0.f, qe = 0.f, qo = 0.f;
#pragma unroll
        for (int f = 0; f < 4; ++f) {
            const float e0 = acc[f][g][0], e1 = acc[f][g][2];
            const float o0 = acc[f][g][1], o1 = acc[f][g][3];
            se += e0 + e1;  qe += e0 * e0 + e1 * e1;
            so += o0 + o1;  qo += o0 * o0 + o1 * o1;
        }
        Psum[gb * 2048 + pr * 128 + cbase + g * 8]     = se;
        Psum[gb * 2048 + pr * 128 + cbase + g * 8 + 1] = so;
        Psq [gb * 2048 + pr * 128 + cbase + g * 8]     = qe;
        Psq [gb * 2048 + pr * 128 + cbase + g * 8 + 1] = qo;
    }
    __syncthreads();

    if (tid < 256) {
        const int sgb = tid >> 7;
        const int col = tid & 127;
        float s = 0.f, s2 = 0.f;
#pragma unroll
        for (int r = 0; r < 16; r++) {
            s  += Psum[sgb * 2048 + r * 128 + col];
            s2 += Psq [sgb * 2048 + r * 128 + col];
        }
        const float mean = s * (1.0f / 128.0f);
        const float var  = s2 * (1.0f / 128.0f) - mean * mean;
        const float sc   = gamma[n0 + col] * rsqrtf(var + EPS_BN);
        cscale[sgb * 128 + col] = sc;
        cshift[sgb * 128 + col] = beta[n0 + col] - mean * sc;
    }
    __syncthreads();

#pragma unroll
    for (int g = 0; g < 4; ++g) {
        const int cl = cbase + g * 8;
        const float2 sc = *(const float2*)&cscale[gb * 128 + cl];
        const float2 sh = *(const float2*)&cshift[gb * 128 + cl];
        const int col = n0 + cl;
#pragma unroll
        for (int f = 0; f < 4; ++f) {
            const int row0 = m0 + warp_m * 64 + f * 16 + (lane >> 2);
#pragma unroll
            for (int h = 0; h < 2; ++h) {
                const size_t row = (size_t)(row0 + h * 8);
                const float2 p = *(const float2*)&priors[row * D_G + col];
                float2 z;
                z.x = fmaf(acc[f][g][h * 2 + 0], sc.x, sh.x) * p.x;
                z.y = fmaf(acc[f][g][h * 2 + 1], sc.y, sh.y) * p.y;
                *(float2*)&g_z[row * D_G + col] = z;
            }
        }
    }
}

// ---------------------------------------------------------------------------
// Kernel 2: sparsemax per row (D=512), Michelot fixed point. Warp per row.
// ---------------------------------------------------------------------------
__global__ __launch_bounds__(256)
void sparsemax_kernel(float* __restrict__ out)
{
    const int gw   = (blockIdx.x * blockDim.x + threadIdx.x) >> 5;
    const int lane = threadIdx.x & 31;
    const float4* zr = (const float4*)(g_z + (size_t)gw * D_G);

    float4 v[4];
#pragma unroll
    for (int c = 0; c < 4; c++) v[c] = zr[c * 32 + lane];

    float mx = fmaxf(fmaxf(v[0].x, v[0].y), fmaxf(v[0].z, v[0].w));
#pragma unroll
    for (int c = 1; c < 4; c++)
        mx = fmaxf(mx, fmaxf(fmaxf(v[c].x, v[c].y), fmaxf(v[c].z, v[c].w)));
#pragma unroll
    for (int o = 16; o > 0; o >>= 1)
        mx = fmaxf(mx, __shfl_xor_sync(0xffffffffu, mx, o));

    float s = 0.0f;
#pragma unroll
    for (int c = 0; c < 4; c++) {
        v[c].x -= mx; v[c].y -= mx; v[c].z -= mx; v[c].w -= mx;
        s += (v[c].x + v[c].y) + (v[c].z + v[c].w);
    }
#pragma unroll
    for (int o = 16; o > 0; o >>= 1)
        s += __shfl_xor_sync(0xffffffffu, s, o);

    float tau = (s - 1.0f) * (1.0f / 512.0f);

    for (int it = 0; it < 64; ++it) {
        float ns = 0.0f;
        unsigned k = 0;
#pragma unroll
        for (int c = 0; c < 4; c++) {
            if (v[c].x > tau) { ns += v[c].x; k++; }
            if (v[c].y > tau) { ns += v[c].y; k++; }
            if (v[c].z > tau) { ns += v[c].z; k++; }
            if (v[c].w > tau) { ns += v[c].w; k++; }
        }
#pragma unroll
        for (int o = 16; o > 0; o >>= 1)
            ns += __shfl_xor_sync(0xffffffffu, ns, o);
        k = __reduce_add_sync(0xffffffffu, k);

        const float nt = (ns - 1.0f) / (float)k;
        if (nt == tau) break;
        tau = nt;
    }

    float4* orow = (float4*)(out + (size_t)gw * D_G);
#pragma unroll
    for (int c = 0; c < 4; c++) {
        float4 r;
        r.x = fmaxf(v[c].x - tau, 0.0f);
        r.y = fmaxf(v[c].y - tau, 0.0f);
        r.z = fmaxf(v[c].z - tau, 0.0f);
        r.w = fmaxf(v[c].w - tau, 0.0f);
        orow[c * 32 + lane] = r;
    }
}

// ---------------------------------------------------------------------------
extern "C" void kernel_launch(void* const* d_in, const int* in_sizes, int n_in,
                              void* d_out, int out_size)
{
    const float* priors = (const float*)d_in[0];   // [B, 512]
    const float* feat   = (const float*)d_in[1];   // [B, 256]
    const float* W      = (const float*)d_in[2];   // [512, 256]
    const float* gamma  = (const float*)d_in[3];   // [512]
    const float* beta   = (const float*)d_in[4];   // [512]
    float* out = (float*)d_out;                    // [B, 512]

    __nv_bfloat16 *ah, *al, *bh, *bl;
    cudaGetSymbolAddress((void**)&ah, g_ah);
    cudaGetSymbolAddress((void**)&al, g_al);
    cudaGetSymbolAddress((void**)&bh, g_bh);
    cudaGetSymbolAddress((void**)&bl, g_bl);

    split_kernel<<<(B_ROWS * D_IN / 4) / 256, 256>>>(feat, ah, al);
    split_kernel<<<(D_G * D_IN / 4) / 256, 256>>>(W, bh, bl);

    cudaFuncSetAttribute(gemm_gbn_mma,
                         cudaFuncAttributeMaxDynamicSharedMemorySize, SMEM_TOTAL);

    dim3 grid1(D_G / 128, B_ROWS / 256);           // (4, 256)
    gemm_gbn_mma<<<grid1, 512, SMEM_TOTAL>>>(priors, gamma, beta);

    sparsemax_kernel<<<(B_ROWS * 32) / 256, 256>>>(out);
}